// round 11
// baseline (speedup 1.0000x reference)
#include <cuda_runtime.h>
#include <cstdint>

typedef unsigned long long u64;

#define Bn 64
#define Gn 200
#define QT 10
#define LH 204                 // h-stride of L (204 mod 32 = 12 -> conflict-free)
#define LQ (8 * LH)            // 1632 q-stride

// ---------------- scratch (static device arrays; no allocation) ----------------
__device__ float g_Q[Bn * Gn * 128];          // [b][g][h*16+k]
__device__ float g_K[Bn * Gn * 128];          // [b][g][h*16+k]
__device__ float g_V[Bn * Gn * 128];          // [b][g][h*16+v]

// ---------------- packed f32x2 helpers ----------------
__device__ __forceinline__ u64 fma2(u64 a, u64 b, u64 c) {
    u64 d; asm("fma.rn.f32x2 %0, %1, %2, %3;" : "=l"(d) : "l"(a), "l"(b), "l"(c)); return d;
}
__device__ __forceinline__ u64 pk(float lo, float hi) {
    u64 d; asm("mov.b64 %0, {%1, %2};" : "=l"(d) : "f"(lo), "f"(hi)); return d;
}
__device__ __forceinline__ float2 up(u64 a) {
    float2 r; asm("mov.b64 {%0, %1}, %2;" : "=f"(r.x), "=f"(r.y) : "l"(a)); return r;
}
__device__ __forceinline__ float hadd(u64 a) { float2 r = up(a); return r.x + r.y; }

__device__ __forceinline__ uint32_t smem_u32(const void* p) {
    uint32_t a;
    asm("{ .reg .u64 t; cvta.to.shared.u64 t, %1; cvt.u32.u64 %0, t; }" : "=r"(a) : "l"(p));
    return a;
}
__device__ __forceinline__ void mbar_wait0(uint32_t mbar) {
    asm volatile(
        "{\n\t.reg .pred P;\n"
        "W%=: mbarrier.try_wait.parity.shared.b64 P, [%0], 0;\n"
        "@!P bra W%=;\n\t}"
        :: "r"(mbar) : "memory");
}

// ================= kernel 1: QKV projections — merged w-loop, single wave =================
// grid (4 gtiles of 50, 64 b); 256 threads; 3 CTAs/SM; 256 blocks < 444 slots = 1 wave.
#define SMEM1 ((8192 + 8320) * 4)

__global__ __launch_bounds__(256, 3) void proj_kernel(
    const float* __restrict__ h_em, const float* __restrict__ Wq,
    const float* __restrict__ Wk, const float* __restrict__ Wv)
{
    extern __shared__ float sm1[];
    float* Wsm = sm1;            // [d][o_local 64]
    float* xs  = sm1 + 8192;     // [d][gl] stride 65

    int t  = threadIdx.x;
    int tx = t & 15, ty = t >> 4;
    int g0 = blockIdx.x * 50;
    int b  = blockIdx.y;

    const float4* xsrc = (const float4*)(h_em + (size_t)(b * Gn + g0) * 128);
    for (int i4 = t; i4 < 1600; i4 += 256) {
        float4 v = xsrc[i4];
        int gl = i4 >> 5, d4 = (i4 & 31) * 4;
        xs[(d4 + 0) * 65 + gl] = v.x;
        xs[(d4 + 1) * 65 + gl] = v.y;
        xs[(d4 + 2) * 65 + gl] = v.z;
        xs[(d4 + 3) * 65 + gl] = v.w;
    }

    #pragma unroll 1
    for (int w = 0; w < 3; w++) {
        const float* W = (w == 0) ? Wq : (w == 1) ? Wk : Wv;
        float* outp    = (w == 0) ? g_Q : (w == 1) ? g_K : g_V;
        #pragma unroll 1
        for (int wh = 0; wh < 2; wh++) {
            __syncthreads();
            for (int idx = t; idx < 8192; idx += 256) {
                int hl = idx >> 11, d = (idx >> 4) & 127, k = idx & 15;
                Wsm[d * 64 + hl * 16 + k] = W[(wh * 4 + hl) * 2048 + d * 16 + k];
            }
            __syncthreads();

            u64 acc[4][2];
            #pragma unroll
            for (int i = 0; i < 4; i++) { acc[i][0] = 0ull; acc[i][1] = 0ull; }

            const u64* Wp = (const u64*)Wsm;
            #pragma unroll 4
            for (int d = 0; d < 128; d++) {
                u64 wv0 = Wp[d * 32 + tx];
                u64 wv1 = Wp[d * 32 + tx + 16];
                #pragma unroll
                for (int i = 0; i < 4; i++) {
                    float x = xs[d * 65 + i * 16 + ty];
                    u64 xv = pk(x, x);
                    acc[i][0] = fma2(xv, wv0, acc[i][0]);
                    acc[i][1] = fma2(xv, wv1, acc[i][1]);
                }
            }
            #pragma unroll
            for (int i = 0; i < 4; i++) {
                int gl = i * 16 + ty;
                if (gl < 50) {
                    float* op = outp + (size_t)(b * Gn + g0 + gl) * 128 + wh * 64 + tx * 2;
                    *(u64*)op        = acc[i][0];
                    *(u64*)(op + 32) = acc[i][1];
                }
            }
        }
    }
}

// ================= kernel 2: fused; route via bulk-async smem staging =================
// grid (20, 64); 512 threads; smem 202752 B; 1 CTA/SM.
#define SMEM2 202752
#define SLAB_BYTES 8000u        // 10 q x 200 g x 4 B per route channel
#define RSM_F 32000             // 16 slabs of 2000 floats

__global__ __launch_bounds__(512, 1) void main_kernel(
    const float* __restrict__ route, const float* __restrict__ W1,
    const float* __restrict__ b1, const float* __restrict__ W2,
    const float* __restrict__ b2, const float* __restrict__ Wo,
    float* __restrict__ out, float* __restrict__ out_route)
{
    extern __shared__ char smraw[];
    float* rsm    = (float*)smraw;            // 32000 f : route [r][q][g]
    float* L      = rsm + RSM_F;              // 16320 f : [q][h][g]
    float* Qsm    = L + 16320;                // 1280 f
    u64*   W1d    = (u64*)(Qsm + 1280);       // 384
    u64*   W2d    = W1d + 384;                // 128
    u64*   b1d    = W2d + 128;                // 16
    u64*   b2d    = b1d + 16;                 // 8
    u64*   mbarp  = b2d + 8;                  // 1 u64 mbarrier
    // overlays into rsm AFTER bulk stores drain:
    float* hp     = rsm;                      // 5632 f
    u64*   headsd = (u64*)(rsm + 5632);       // 1280 u64
    u64*   scratch= (u64*)(rsm + 8192);       // 1280 u64

    int t  = threadIdx.x;
    int b  = blockIdx.y;
    int q0 = blockIdx.x * QT;
    uint32_t mbar = smem_u32(mbarp);
    uint32_t rsm_a = smem_u32(rsm);

    // ---- phase 0: stage Q (chunk-permuted), dup weight tables, init mbarrier ----
    const float4* Qs = (const float4*)(g_Q + (size_t)(b * Gn + q0) * 128);
    for (int i4 = t; i4 < 320; i4 += 512) {
        float4 v = Qs[i4];
        int q = i4 >> 5, rem = i4 & 31, h = rem >> 2, c = rem & 3;
        int chunk = h * 4 + ((c + (h >> 1)) & 3);
        *(float4*)(Qsm + q * 128 + chunk * 4) = v;
    }
    if (t < 384) W1d[t] = pk(W1[t], W1[t]);
    if (t >= 384 && t < 512) { int i = t - 384; W2d[i] = pk(W2[i], W2[i]); }
    if (t < 16)  { b1d[t] = pk(b1[t], b1[t]); }
    if (t >= 16 && t < 24) { int i = t - 16; b2d[i] = pk(b2[i], b2[i]); }
    if (t == 0)
        asm volatile("mbarrier.init.shared.b64 [%0], 1;" :: "r"(mbar) : "memory");
    __syncthreads();

    // ---- kick off 16 bulk route loads (one thread) ----
    if (t == 0) {
        asm volatile("mbarrier.arrive.expect_tx.shared.b64 _, [%0], %1;"
                     :: "r"(mbar), "r"(16u * SLAB_BYTES) : "memory");
        const float* base = route + (size_t)(b * Gn + q0) * Gn;
        #pragma unroll
        for (int r = 0; r < 16; r++) {
            asm volatile(
                "cp.async.bulk.shared::cta.global.mbarrier::complete_tx::bytes [%0], [%1], %2, [%3];"
                :: "r"(rsm_a + r * SLAB_BYTES), "l"(base + (size_t)r * 2560000),
                   "r"(SLAB_BYTES), "r"(mbar) : "memory");
        }
    }

    // ---- phase 1a: raw qk -> L (overlaps bulk loads) ----
    for (int u = t; u < 1600; u += 512) {
        int g = u >> 3, h = u & 7;
        const ulonglong2* Kp = (const ulonglong2*)(g_K + (size_t)(b * Gn + g) * 128 + h * 16);
        ulonglong2 kv[4];
        #pragma unroll
        for (int i = 0; i < 4; i++) kv[i] = Kp[i];
        int h2 = h >> 1;
        float* Ld = L + h * LH + g;
        #pragma unroll
        for (int q = 0; q < QT; q++) {
            const float* Qr = Qsm + q * 128;
            u64 a = 0ull;
            #pragma unroll
            for (int c = 0; c < 4; c++) {
                int p = h * 4 + ((c + h2) & 3);
                ulonglong2 qc = *(const ulonglong2*)(Qr + p * 4);
                a = fma2(kv[c].x, qc.x, a);
                a = fma2(kv[c].y, qc.y, a);
            }
            Ld[q * LQ] = hadd(a);
        }
    }
    __syncthreads();
    mbar_wait0(mbar);

    // ---- passthrough: 16 bulk stores smem -> out_route (drain during later phases) ----
    if (t == 0 && out_route) {
        asm volatile("fence.proxy.async.shared::cta;" ::: "memory");
        float* obase = out_route + (size_t)(b * Gn + q0) * Gn;
        #pragma unroll
        for (int r = 0; r < 16; r++) {
            asm volatile(
                "cp.async.bulk.global.shared::cta.bulk_group [%0], [%1], %2;"
                :: "l"(obase + (size_t)r * 2560000), "r"(rsm_a + r * SLAB_BYTES),
                   "r"(SLAB_BYTES) : "memory");
        }
        asm volatile("cp.async.bulk.commit_group;" ::: "memory");
    }

    // ---- phase 1b: g-QUAD items, route from smem, weights amortized over 4 positions ----
    const ulonglong2* W1p = (const ulonglong2*)W1d;
    const ulonglong2* W2p = (const ulonglong2*)W2d;
    if (t < 500) {
        int q  = t / 50;
        int gq = t - q * 50;
        int g  = gq * 4;

        u64 hidA[16], hidB[16];
        #pragma unroll
        for (int j = 0; j < 16; j++) { hidA[j] = b1d[j]; hidB[j] = b1d[j]; }

        float* Lqg = L + q * LQ + g;
        #pragma unroll
        for (int hh = 0; hh < 4; hh++) {
            ulonglong2 x0 = *(const ulonglong2*)(Lqg + (2 * hh) * LH);      // h=2hh: (g,g+1),(g+2,g+3)
            ulonglong2 x1 = *(const ulonglong2*)(Lqg + (2 * hh + 1) * LH);
            #pragma unroll
            for (int j = 0; j < 16; j++) {
                ulonglong2 w = W1p[j * 12 + hh];
                hidA[j] = fma2(x0.x, w.x, hidA[j]);
                hidB[j] = fma2(x0.y, w.x, hidB[j]);
                hidA[j] = fma2(x1.x, w.y, hidA[j]);
                hidB[j] = fma2(x1.y, w.y, hidB[j]);
            }
        }
        const float* rq = rsm + q * 200 + g;
        #pragma unroll
        for (int rr = 0; rr < 8; rr++) {
            float4 c0 = *(const float4*)(rq + (2 * rr) * 2000);     // channel 2rr, g..g+3
            float4 c1 = *(const float4*)(rq + (2 * rr + 1) * 2000);
            u64 a0 = pk(c0.x, c0.y), b0 = pk(c0.z, c0.w);
            u64 a1 = pk(c1.x, c1.y), b1v = pk(c1.z, c1.w);
            #pragma unroll
            for (int j = 0; j < 16; j++) {
                ulonglong2 w = W1p[j * 12 + 4 + rr];
                hidA[j] = fma2(a0, w.x, hidA[j]);
                hidB[j] = fma2(b0, w.x, hidB[j]);
                hidA[j] = fma2(a1, w.y, hidA[j]);
                hidB[j] = fma2(b1v, w.y, hidB[j]);
            }
        }
        #pragma unroll
        for (int j = 0; j < 16; j++) {
            float2 va = up(hidA[j]);
            hidA[j] = pk(fmaxf(va.x, 0.f), fmaxf(va.y, 0.f));
            float2 vb = up(hidB[j]);
            hidB[j] = pk(fmaxf(vb.x, 0.f), fmaxf(vb.y, 0.f));
        }
        #pragma unroll
        for (int h = 0; h < 8; h++) {
            u64 aA = b2d[h], aB = b2d[h];
            #pragma unroll
            for (int j = 0; j < 16; j += 2) {
                ulonglong2 w = W2p[(h * 16 + j) >> 1];
                aA = fma2(hidA[j], w.x, aA);
                aB = fma2(hidB[j], w.x, aB);
                aA = fma2(hidA[j + 1], w.y, aA);
                aB = fma2(hidB[j + 1], w.y, aB);
            }
            ulonglong2 st; st.x = aA; st.y = aB;
            *(ulonglong2*)(Lqg + h * LH) = st;
        }
    }
    __syncthreads();

    // ---- phase 2: softmax over g, one warp per (q,h) row; 80 rows / 16 warps ----
    {
        int warp = t >> 5, lane = t & 31;
        for (int row = warp; row < 80; row += 16) {
            float* Lr = L + (row >> 3) * LQ + (row & 7) * LH;
            float m = -1e30f;
            for (int i = lane; i < 200; i += 32) m = fmaxf(m, Lr[i]);
            #pragma unroll
            for (int o = 16; o > 0; o >>= 1) m = fmaxf(m, __shfl_xor_sync(0xffffffffu, m, o));
            float s = 0.f;
            for (int i = lane; i < 200; i += 32) { float e = __expf(Lr[i] - m); Lr[i] = e; s += e; }
            #pragma unroll
            for (int o = 16; o > 0; o >>= 1) s += __shfl_xor_sync(0xffffffffu, s, o);
            float inv = 1.f / s;
            for (int i = lane; i < 200; i += 32) Lr[i] *= inv;
        }
    }
    // drain bulk stores before overlaying rsm with hp/headsd
    if (t == 0 && out_route)
        asm volatile("cp.async.bulk.wait_group 0;" ::: "memory");
    __syncthreads();

    // ---- phase 3: heads[q][hv] = sum_g p[q][h][g] * V[g][hv]; slices {52,52,48,48} ----
    {
        int s = t >> 7, hv = t & 127, h = hv >> 4;
        int base = s * 48 + ((s < 2) ? s * 4 : 8);   // 0, 52, 104, 152
        int len  = (s < 2) ? 52 : 48;
        const float* Vp = g_V + (size_t)(b * Gn + base) * 128 + hv;
        const float* Lh = L + h * LH + base;
        u64 acc[QT];
        #pragma unroll
        for (int q = 0; q < QT; q++) acc[q] = 0ull;
        for (int i = 0; i < len; i += 4) {
            float v0 = Vp[(i + 0) * 128], v1 = Vp[(i + 1) * 128];
            float v2 = Vp[(i + 2) * 128], v3 = Vp[(i + 3) * 128];
            u64 va = pk(v0, v1), vb = pk(v2, v3);
            #pragma unroll
            for (int q = 0; q < QT; q++) {
                ulonglong2 p = *(const ulonglong2*)(Lh + q * LQ + i);
                acc[q] = fma2(p.x, va, acc[q]);
                acc[q] = fma2(p.y, vb, acc[q]);
            }
        }
        float* hpd = hp + (s * 128 + hv) * 11;
        #pragma unroll
        for (int q = 0; q < QT; q++) hpd[q] = hadd(acc[q]);
    }
    __syncthreads();
    if (t < 128) {
        #pragma unroll
        for (int q = 0; q < QT; q++) {
            float v = hp[t * 11 + q] + hp[(128 + t) * 11 + q]
                    + hp[(256 + t) * 11 + q] + hp[(384 + t) * 11 + q];
            headsd[q * 128 + t] = pk(v, v);
        }
    }
    __syncthreads();

    // ---- epilogue: Wo-reuse. 128 threads: (hv-half, e-pair), all 10 q per Wo load ----
    if (t < 128) {
        int half = t >> 6, ep = t & 63;
        const u64* Wop = (const u64*)Wo + ep;        // row stride 64 u64
        u64 acc[QT];
        #pragma unroll
        for (int q = 0; q < QT; q++) acc[q] = 0ull;
        int hv0 = half * 64;
        for (int hv = hv0; hv < hv0 + 64; hv += 2) {
            u64 w0 = Wop[hv * 64];
            u64 w1 = Wop[(hv + 1) * 64];
            #pragma unroll
            for (int q = 0; q < QT; q++) {
                ulonglong2 hh = *(const ulonglong2*)(headsd + q * 128 + hv);
                acc[q] = fma2(hh.x, w0, acc[q]);
                acc[q] = fma2(hh.y, w1, acc[q]);
            }
        }
        #pragma unroll
        for (int q = 0; q < QT; q++) scratch[t * QT + q] = acc[q];
    }
    __syncthreads();
    if (t < 64) {
        #pragma unroll
        for (int q = 0; q < QT; q++) {
            float2 a = up(scratch[t * QT + q]);
            float2 c = up(scratch[(64 + t) * QT + q]);
            float2 r; r.x = a.x + c.x; r.y = a.y + c.y;
            *(float2*)(out + (size_t)(b * Gn + q0 + q) * 128 + t * 2) = r;
        }
    }
}

extern "C" void kernel_launch(void* const* d_in, const int* in_sizes, int n_in,
                              void* d_out, int out_size) {
    const float* h_em  = (const float*)d_in[0];
    const float* route = (const float*)d_in[1];
    const float* Wq    = (const float*)d_in[2];
    const float* Wk    = (const float*)d_in[3];
    const float* Wv    = (const float*)d_in[4];
    const float* W1    = (const float*)d_in[5];
    const float* b1    = (const float*)d_in[6];
    const float* W2    = (const float*)d_in[7];
    const float* b2    = (const float*)d_in[8];
    const float* Wo    = (const float*)d_in[9];
    float* out = (float*)d_out;

    float* out_route = nullptr;
    if (out_size >= 1638400 + 40960000) out_route = out + 1638400;

    static bool attr_done = false;
    if (!attr_done) {
        cudaFuncSetAttribute(proj_kernel, cudaFuncAttributeMaxDynamicSharedMemorySize, SMEM1);
        cudaFuncSetAttribute(main_kernel, cudaFuncAttributeMaxDynamicSharedMemorySize, SMEM2);
        attr_done = true;
    }

    dim3 grid1(4, Bn);
    proj_kernel<<<grid1, 256, SMEM1>>>(h_em, Wq, Wk, Wv);
    dim3 grid2(Gn / QT, Bn);
    main_kernel<<<grid2, 512, SMEM2>>>(route, W1, b1, W2, b2, Wo, out, out_route);
}

// round 12
// speedup vs baseline: 1.0045x; 1.0045x over previous
#include <cuda_runtime.h>
#include <cstdint>

typedef unsigned long long u64;

#define Bn 64
#define Gn 200
#define QT 5
#define LH 204                 // h-stride of L (204 mod 32 = 12 -> conflict-free)
#define LQ (8 * LH)            // 1632 q-stride

// ---------------- scratch (static device arrays; no allocation) ----------------
__device__ float g_Q[Bn * Gn * 128];          // [b][g][h*16+k]
__device__ float g_K[Bn * Gn * 128];          // [b][g][h*16+k]
__device__ float g_V[Bn * Gn * 128];          // [b][g][h*16+v]

// ---------------- packed f32x2 helpers ----------------
__device__ __forceinline__ u64 fma2(u64 a, u64 b, u64 c) {
    u64 d; asm("fma.rn.f32x2 %0, %1, %2, %3;" : "=l"(d) : "l"(a), "l"(b), "l"(c)); return d;
}
__device__ __forceinline__ u64 pk(float lo, float hi) {
    u64 d; asm("mov.b64 %0, {%1, %2};" : "=l"(d) : "f"(lo), "f"(hi)); return d;
}
__device__ __forceinline__ float2 up(u64 a) {
    float2 r; asm("mov.b64 {%0, %1}, %2;" : "=f"(r.x), "=f"(r.y) : "l"(a)); return r;
}
__device__ __forceinline__ float hadd(u64 a) { float2 r = up(a); return r.x + r.y; }

__device__ __forceinline__ uint32_t smem_u32(const void* p) {
    uint32_t a;
    asm("{ .reg .u64 t; cvta.to.shared.u64 t, %1; cvt.u32.u64 %0, t; }" : "=r"(a) : "l"(p));
    return a;
}
__device__ __forceinline__ void mbar_wait0(uint32_t mbar) {
    asm volatile(
        "{\n\t.reg .pred P;\n"
        "W%=: mbarrier.try_wait.parity.shared.b64 P, [%0], 0;\n"
        "@!P bra W%=;\n\t}"
        :: "r"(mbar) : "memory");
}

// ================= kernel 1: QKV projections — merged w-loop, single wave =================
#define SMEM1 ((8192 + 8320) * 4)

__global__ __launch_bounds__(256, 3) void proj_kernel(
    const float* __restrict__ h_em, const float* __restrict__ Wq,
    const float* __restrict__ Wk, const float* __restrict__ Wv)
{
    extern __shared__ float sm1[];
    float* Wsm = sm1;            // [d][o_local 64]
    float* xs  = sm1 + 8192;     // [d][gl] stride 65

    int t  = threadIdx.x;
    int tx = t & 15, ty = t >> 4;
    int g0 = blockIdx.x * 50;
    int b  = blockIdx.y;

    const float4* xsrc = (const float4*)(h_em + (size_t)(b * Gn + g0) * 128);
    for (int i4 = t; i4 < 1600; i4 += 256) {
        float4 v = xsrc[i4];
        int gl = i4 >> 5, d4 = (i4 & 31) * 4;
        xs[(d4 + 0) * 65 + gl] = v.x;
        xs[(d4 + 1) * 65 + gl] = v.y;
        xs[(d4 + 2) * 65 + gl] = v.z;
        xs[(d4 + 3) * 65 + gl] = v.w;
    }

    #pragma unroll 1
    for (int w = 0; w < 3; w++) {
        const float* W = (w == 0) ? Wq : (w == 1) ? Wk : Wv;
        float* outp    = (w == 0) ? g_Q : (w == 1) ? g_K : g_V;
        #pragma unroll 1
        for (int wh = 0; wh < 2; wh++) {
            __syncthreads();
            for (int idx = t; idx < 8192; idx += 256) {
                int hl = idx >> 11, d = (idx >> 4) & 127, k = idx & 15;
                Wsm[d * 64 + hl * 16 + k] = W[(wh * 4 + hl) * 2048 + d * 16 + k];
            }
            __syncthreads();

            u64 acc[4][2];
            #pragma unroll
            for (int i = 0; i < 4; i++) { acc[i][0] = 0ull; acc[i][1] = 0ull; }

            const u64* Wp = (const u64*)Wsm;
            #pragma unroll 4
            for (int d = 0; d < 128; d++) {
                u64 wv0 = Wp[d * 32 + tx];
                u64 wv1 = Wp[d * 32 + tx + 16];
                #pragma unroll
                for (int i = 0; i < 4; i++) {
                    float x = xs[d * 65 + i * 16 + ty];
                    u64 xv = pk(x, x);
                    acc[i][0] = fma2(xv, wv0, acc[i][0]);
                    acc[i][1] = fma2(xv, wv1, acc[i][1]);
                }
            }
            #pragma unroll
            for (int i = 0; i < 4; i++) {
                int gl = i * 16 + ty;
                if (gl < 50) {
                    float* op = outp + (size_t)(b * Gn + g0 + gl) * 128 + wh * 64 + tx * 2;
                    *(u64*)op        = acc[i][0];
                    *(u64*)(op + 32) = acc[i][1];
                }
            }
        }
    }
}

// ================= kernel 2: fused; TMA route staging + 2 CTAs/SM =================
// grid (40, 64); 512 threads; smem ~103.5 KB/CTA -> 2 CTAs/SM, 32 warps.
#define SLAB_BYTES 4000u        // 5 q x 200 g x 4 B per route channel
#define RSM_F 16000             // 16 slabs of 1000 floats
#define SMEM2 (RSM_F * 4 + 8160 * 4 + 640 * 4 + (384 + 128 + 16 + 8 + 8) * 8)

__global__ __launch_bounds__(512, 2) void main_kernel(
    const float* __restrict__ route, const float* __restrict__ W1,
    const float* __restrict__ b1, const float* __restrict__ W2,
    const float* __restrict__ b2, const float* __restrict__ Wo,
    float* __restrict__ out, float* __restrict__ out_route)
{
    extern __shared__ char smraw[];
    float* rsm    = (float*)smraw;            // 16000 f : route [r][q][g]
    float* L      = rsm + RSM_F;              // 8160 f : [q][h][g]
    float* Qsm    = L + 8160;                 // 640 f
    u64*   W1d    = (u64*)(Qsm + 640);        // 384
    u64*   W2d    = W1d + 384;                // 128
    u64*   b1d    = W2d + 128;                // 16
    u64*   b2d    = b1d + 16;                 // 8
    u64*   mbarp  = b2d + 8;                  // mbarrier
    // overlays into rsm AFTER bulk stores drain:
    float* hp     = rsm;                      // [4][128][7] = 3584 f
    u64*   headsd = (u64*)(rsm + 3584);       // 640 u64
    u64*   scratch= (u64*)(rsm + 3584 + 1280);// 640 u64

    int t  = threadIdx.x;
    int b  = blockIdx.y;
    int q0 = blockIdx.x * QT;
    uint32_t mbar = smem_u32(mbarp);
    uint32_t rsm_a = smem_u32(rsm);

    // ---- phase 0: stage Q (chunk-permuted), dup weight tables, init mbarrier ----
    const float4* Qs = (const float4*)(g_Q + (size_t)(b * Gn + q0) * 128);
    for (int i4 = t; i4 < 160; i4 += 512) {
        float4 v = Qs[i4];
        int q = i4 >> 5, rem = i4 & 31, h = rem >> 2, c = rem & 3;
        int chunk = h * 4 + ((c + (h >> 1)) & 3);
        *(float4*)(Qsm + q * 128 + chunk * 4) = v;
    }
    if (t < 384) W1d[t] = pk(W1[t], W1[t]);
    if (t >= 384 && t < 512) { int i = t - 384; W2d[i] = pk(W2[i], W2[i]); }
    if (t < 16)  { b1d[t] = pk(b1[t], b1[t]); }
    if (t >= 16 && t < 24) { int i = t - 16; b2d[i] = pk(b2[i], b2[i]); }
    if (t == 0)
        asm volatile("mbarrier.init.shared.b64 [%0], 1;" :: "r"(mbar) : "memory");
    __syncthreads();

    // ---- kick off 16 bulk route loads (one thread) ----
    if (t == 0) {
        asm volatile("mbarrier.arrive.expect_tx.shared.b64 _, [%0], %1;"
                     :: "r"(mbar), "r"(16u * SLAB_BYTES) : "memory");
        const float* base = route + (size_t)(b * Gn + q0) * Gn;
        #pragma unroll
        for (int r = 0; r < 16; r++) {
            asm volatile(
                "cp.async.bulk.shared::cta.global.mbarrier::complete_tx::bytes [%0], [%1], %2, [%3];"
                :: "r"(rsm_a + r * SLAB_BYTES), "l"(base + (size_t)r * 2560000),
                   "r"(SLAB_BYTES), "r"(mbar) : "memory");
        }
    }

    // ---- phase 1a: raw qk -> L (overlaps bulk loads) ----
    for (int u = t; u < 1600; u += 512) {
        int g = u >> 3, h = u & 7;
        const ulonglong2* Kp = (const ulonglong2*)(g_K + (size_t)(b * Gn + g) * 128 + h * 16);
        ulonglong2 kv[4];
        #pragma unroll
        for (int i = 0; i < 4; i++) kv[i] = Kp[i];
        int h2 = h >> 1;
        float* Ld = L + h * LH + g;
        #pragma unroll
        for (int q = 0; q < QT; q++) {
            const float* Qr = Qsm + q * 128;
            u64 a = 0ull;
            #pragma unroll
            for (int c = 0; c < 4; c++) {
                int p = h * 4 + ((c + h2) & 3);
                ulonglong2 qc = *(const ulonglong2*)(Qr + p * 4);
                a = fma2(kv[c].x, qc.x, a);
                a = fma2(kv[c].y, qc.y, a);
            }
            Ld[q * LQ] = hadd(a);
        }
    }
    __syncthreads();
    mbar_wait0(mbar);

    // ---- passthrough: 16 bulk stores smem -> out_route ----
    if (t == 0 && out_route) {
        asm volatile("fence.proxy.async.shared::cta;" ::: "memory");
        float* obase = out_route + (size_t)(b * Gn + q0) * Gn;
        #pragma unroll
        for (int r = 0; r < 16; r++) {
            asm volatile(
                "cp.async.bulk.global.shared::cta.bulk_group [%0], [%1], %2;"
                :: "l"(obase + (size_t)r * 2560000), "r"(rsm_a + r * SLAB_BYTES),
                   "r"(SLAB_BYTES) : "memory");
        }
        asm volatile("cp.async.bulk.commit_group;" ::: "memory");
    }

    // ---- phase 1b: g-PAIR items; route from smem; one balanced round (500/512) ----
    const ulonglong2* W1p = (const ulonglong2*)W1d;
    const ulonglong2* W2p = (const ulonglong2*)W2d;
    if (t < 500) {
        int q  = t / 100;
        int gp = t - q * 100;
        int g  = gp * 2;

        u64 hid[16];
        #pragma unroll
        for (int j = 0; j < 16; j++) hid[j] = b1d[j];

        float* Lqg = L + q * LQ + g;
        #pragma unroll
        for (int hh = 0; hh < 4; hh++) {
            u64 x0 = *(const u64*)(Lqg + (2 * hh) * LH);
            u64 x1 = *(const u64*)(Lqg + (2 * hh + 1) * LH);
            #pragma unroll
            for (int j = 0; j < 16; j++) {
                ulonglong2 w = W1p[j * 12 + hh];
                hid[j] = fma2(x0, w.x, hid[j]);
                hid[j] = fma2(x1, w.y, hid[j]);
            }
        }
        // route channels 2rr,2rr+1 = input pairs 4+rr (rr = 0..7)
        const float* rq = rsm + q * 200 + g;
        #pragma unroll
        for (int rr = 0; rr < 8; rr++) {
            u64 r0 = *(const u64*)(rq + (2 * rr) * 1000);
            u64 r1 = *(const u64*)(rq + (2 * rr + 1) * 1000);
            #pragma unroll
            for (int j = 0; j < 16; j++) {
                ulonglong2 w = W1p[j * 12 + 4 + rr];
                hid[j] = fma2(r0, w.x, hid[j]);
                hid[j] = fma2(r1, w.y, hid[j]);
            }
        }
        #pragma unroll
        for (int j = 0; j < 16; j++) {
            float2 v = up(hid[j]);
            hid[j] = pk(fmaxf(v.x, 0.f), fmaxf(v.y, 0.f));
        }
        #pragma unroll
        for (int h = 0; h < 8; h++) {
            u64 a = b2d[h];
            #pragma unroll
            for (int j = 0; j < 16; j += 2) {
                ulonglong2 w = W2p[(h * 16 + j) >> 1];
                a = fma2(hid[j], w.x, a);
                a = fma2(hid[j + 1], w.y, a);
            }
            *(u64*)(Lqg + h * LH) = a;
        }
    }
    __syncthreads();

    // ---- phase 2: softmax over g, one warp per (q,h) row; 40 rows / 16 warps ----
    {
        int warp = t >> 5, lane = t & 31;
        for (int row = warp; row < 40; row += 16) {
            float* Lr = L + (row >> 3) * LQ + (row & 7) * LH;
            float m = -1e30f;
            for (int i = lane; i < 200; i += 32) m = fmaxf(m, Lr[i]);
            #pragma unroll
            for (int o = 16; o > 0; o >>= 1) m = fmaxf(m, __shfl_xor_sync(0xffffffffu, m, o));
            float s = 0.f;
            for (int i = lane; i < 200; i += 32) { float e = __expf(Lr[i] - m); Lr[i] = e; s += e; }
            #pragma unroll
            for (int o = 16; o > 0; o >>= 1) s += __shfl_xor_sync(0xffffffffu, s, o);
            float inv = 1.f / s;
            for (int i = lane; i < 200; i += 32) Lr[i] *= inv;
        }
    }
    // drain bulk stores before overlaying rsm with hp/headsd
    if (t == 0 && out_route)
        asm volatile("cp.async.bulk.wait_group 0;" ::: "memory");
    __syncthreads();

    // ---- phase 3: heads[q][hv] = sum_g p[q][h][g] * V[g][hv]; slices {52,52,48,48} ----
    {
        int s = t >> 7, hv = t & 127, h = hv >> 4;
        int base = s * 48 + ((s < 2) ? s * 4 : 8);   // 0, 52, 104, 152
        int len  = (s < 2) ? 52 : 48;
        const float* Vp = g_V + (size_t)(b * Gn + base) * 128 + hv;
        const float* Lh = L + h * LH + base;
        u64 acc[QT];
        #pragma unroll
        for (int q = 0; q < QT; q++) acc[q] = 0ull;
        for (int i = 0; i < len; i += 4) {
            float v0 = Vp[(i + 0) * 128], v1 = Vp[(i + 1) * 128];
            float v2 = Vp[(i + 2) * 128], v3 = Vp[(i + 3) * 128];
            u64 va = pk(v0, v1), vb = pk(v2, v3);
            #pragma unroll
            for (int q = 0; q < QT; q++) {
                ulonglong2 p = *(const ulonglong2*)(Lh + q * LQ + i);
                acc[q] = fma2(p.x, va, acc[q]);
                acc[q] = fma2(p.y, vb, acc[q]);
            }
        }
        float* hpd = hp + (s * 128 + hv) * 7;
        #pragma unroll
        for (int q = 0; q < QT; q++) hpd[q] = hadd(acc[q]);
    }
    __syncthreads();
    if (t < 128) {
        #pragma unroll
        for (int q = 0; q < QT; q++) {
            float v = hp[t * 7 + q] + hp[(128 + t) * 7 + q]
                    + hp[(256 + t) * 7 + q] + hp[(384 + t) * 7 + q];
            headsd[q * 128 + t] = pk(v, v);
        }
    }
    __syncthreads();

    // ---- epilogue: Wo-reuse. 128 threads: (hv-half, e-pair), all q per Wo load ----
    if (t < 128) {
        int half = t >> 6, ep = t & 63;
        const u64* Wop = (const u64*)Wo + ep;        // row stride 64 u64
        u64 acc[QT];
        #pragma unroll
        for (int q = 0; q < QT; q++) acc[q] = 0ull;
        int hv0 = half * 64;
        for (int hv = hv0; hv < hv0 + 64; hv += 2) {
            u64 w0 = Wop[hv * 64];
            u64 w1 = Wop[(hv + 1) * 64];
            #pragma unroll
            for (int q = 0; q < QT; q++) {
                ulonglong2 hh = *(const ulonglong2*)(headsd + q * 128 + hv);
                acc[q] = fma2(hh.x, w0, acc[q]);
                acc[q] = fma2(hh.y, w1, acc[q]);
            }
        }
        #pragma unroll
        for (int q = 0; q < QT; q++) scratch[t * QT + q] = acc[q];
    }
    __syncthreads();
    if (t < 64) {
        #pragma unroll
        for (int q = 0; q < QT; q++) {
            float2 a = up(scratch[t * QT + q]);
            float2 c = up(scratch[(64 + t) * QT + q]);
            float2 r; r.x = a.x + c.x; r.y = a.y + c.y;
            *(float2*)(out + (size_t)(b * Gn + q0 + q) * 128 + t * 2) = r;
        }
    }
}

extern "C" void kernel_launch(void* const* d_in, const int* in_sizes, int n_in,
                              void* d_out, int out_size) {
    const float* h_em  = (const float*)d_in[0];
    const float* route = (const float*)d_in[1];
    const float* Wq    = (const float*)d_in[2];
    const float* Wk    = (const float*)d_in[3];
    const float* Wv    = (const float*)d_in[4];
    const float* W1    = (const float*)d_in[5];
    const float* b1    = (const float*)d_in[6];
    const float* W2    = (const float*)d_in[7];
    const float* b2    = (const float*)d_in[8];
    const float* Wo    = (const float*)d_in[9];
    float* out = (float*)d_out;

    float* out_route = nullptr;
    if (out_size >= 1638400 + 40960000) out_route = out + 1638400;

    static bool attr_done = false;
    if (!attr_done) {
        cudaFuncSetAttribute(proj_kernel, cudaFuncAttributeMaxDynamicSharedMemorySize, SMEM1);
        cudaFuncSetAttribute(main_kernel, cudaFuncAttributeMaxDynamicSharedMemorySize, SMEM2);
        attr_done = true;
    }

    dim3 grid1(4, Bn);
    proj_kernel<<<grid1, 256, SMEM1>>>(h_em, Wq, Wk, Wv);
    dim3 grid2(Gn / QT, Bn);
    main_kernel<<<grid2, 512, SMEM2>>>(route, W1, b1, W2, b2, Wo, out, out_route);
}

// round 13
// speedup vs baseline: 1.0082x; 1.0036x over previous
#include <cuda_runtime.h>
#include <cstdint>

typedef unsigned long long u64;

#define Bn 64
#define Gn 200
#define QT 5
#define LH 204                 // h-stride of L (204 mod 32 = 12 -> conflict-free)
#define LQ (8 * LH)            // 1632 q-stride
#define HSTR 1002              // hidbuf j-stride (1002 mod 32 = 10 -> jg banks distinct)

// ---------------- scratch (static device arrays; no allocation) ----------------
__device__ float g_Q[Bn * Gn * 128];          // [b][g][h*16+k]
__device__ float g_K[Bn * Gn * 128];          // [b][g][h*16+k]
__device__ float g_V[Bn * Gn * 128];          // [b][g][h*16+v]

// ---------------- packed f32x2 helpers ----------------
__device__ __forceinline__ u64 fma2(u64 a, u64 b, u64 c) {
    u64 d; asm("fma.rn.f32x2 %0, %1, %2, %3;" : "=l"(d) : "l"(a), "l"(b), "l"(c)); return d;
}
__device__ __forceinline__ u64 pk(float lo, float hi) {
    u64 d; asm("mov.b64 %0, {%1, %2};" : "=l"(d) : "f"(lo), "f"(hi)); return d;
}
__device__ __forceinline__ float2 up(u64 a) {
    float2 r; asm("mov.b64 {%0, %1}, %2;" : "=f"(r.x), "=f"(r.y) : "l"(a)); return r;
}
__device__ __forceinline__ float hadd(u64 a) { float2 r = up(a); return r.x + r.y; }
__device__ __forceinline__ u64 relu2(u64 a) {
    float2 v = up(a); return pk(fmaxf(v.x, 0.f), fmaxf(v.y, 0.f));
}

__device__ __forceinline__ uint32_t smem_u32(const void* p) {
    uint32_t a;
    asm("{ .reg .u64 t; cvta.to.shared.u64 t, %1; cvt.u32.u64 %0, t; }" : "=r"(a) : "l"(p));
    return a;
}
__device__ __forceinline__ void mbar_wait0(uint32_t mbar) {
    asm volatile(
        "{\n\t.reg .pred P;\n"
        "W%=: mbarrier.try_wait.parity.shared.b64 P, [%0], 0;\n"
        "@!P bra W%=;\n\t}"
        :: "r"(mbar) : "memory");
}

// ================= kernel 1: QKV projections — merged w-loop, single wave =================
#define SMEM1 ((8192 + 8320) * 4)

__global__ __launch_bounds__(256, 3) void proj_kernel(
    const float* __restrict__ h_em, const float* __restrict__ Wq,
    const float* __restrict__ Wk, const float* __restrict__ Wv)
{
    extern __shared__ float sm1[];
    float* Wsm = sm1;            // [d][o_local 64]
    float* xs  = sm1 + 8192;     // [d][gl] stride 65

    int t  = threadIdx.x;
    int tx = t & 15, ty = t >> 4;
    int g0 = blockIdx.x * 50;
    int b  = blockIdx.y;

    const float4* xsrc = (const float4*)(h_em + (size_t)(b * Gn + g0) * 128);
    for (int i4 = t; i4 < 1600; i4 += 256) {
        float4 v = xsrc[i4];
        int gl = i4 >> 5, d4 = (i4 & 31) * 4;
        xs[(d4 + 0) * 65 + gl] = v.x;
        xs[(d4 + 1) * 65 + gl] = v.y;
        xs[(d4 + 2) * 65 + gl] = v.z;
        xs[(d4 + 3) * 65 + gl] = v.w;
    }

    #pragma unroll 1
    for (int w = 0; w < 3; w++) {
        const float* W = (w == 0) ? Wq : (w == 1) ? Wk : Wv;
        float* outp    = (w == 0) ? g_Q : (w == 1) ? g_K : g_V;
        #pragma unroll 1
        for (int wh = 0; wh < 2; wh++) {
            __syncthreads();
            for (int idx = t; idx < 8192; idx += 256) {
                int hl = idx >> 11, d = (idx >> 4) & 127, k = idx & 15;
                Wsm[d * 64 + hl * 16 + k] = W[(wh * 4 + hl) * 2048 + d * 16 + k];
            }
            __syncthreads();

            u64 acc[4][2];
            #pragma unroll
            for (int i = 0; i < 4; i++) { acc[i][0] = 0ull; acc[i][1] = 0ull; }

            const u64* Wp = (const u64*)Wsm;
            #pragma unroll 4
            for (int d = 0; d < 128; d++) {
                u64 wv0 = Wp[d * 32 + tx];
                u64 wv1 = Wp[d * 32 + tx + 16];
                #pragma unroll
                for (int i = 0; i < 4; i++) {
                    float x = xs[d * 65 + i * 16 + ty];
                    u64 xv = pk(x, x);
                    acc[i][0] = fma2(xv, wv0, acc[i][0]);
                    acc[i][1] = fma2(xv, wv1, acc[i][1]);
                }
            }
            #pragma unroll
            for (int i = 0; i < 4; i++) {
                int gl = i * 16 + ty;
                if (gl < 50) {
                    float* op = outp + (size_t)(b * Gn + g0 + gl) * 128 + wh * 64 + tx * 2;
                    *(u64*)op        = acc[i][0];
                    *(u64*)(op + 32) = acc[i][1];
                }
            }
        }
    }
}

// ================= kernel 2: fused; TMA route staging + GEMM-form MLP =================
// grid (40, 64); 512 threads; smem ~103.7 KB/CTA -> 2 CTAs/SM, 32 warps.
#define SLAB_BYTES 4000u        // 5 q x 200 g x 4 B per route channel
#define RSM_F 16032             // 16 slabs of 1000 floats (+pad for hidbuf overlay)
#define SMEM2 ((RSM_F + 8160 + 640) * 4 + (384 + 128 + 16 + 8 + 8) * 8)

__global__ __launch_bounds__(512, 2) void main_kernel(
    const float* __restrict__ route, const float* __restrict__ W1,
    const float* __restrict__ b1, const float* __restrict__ W2,
    const float* __restrict__ b2, const float* __restrict__ Wo,
    float* __restrict__ out, float* __restrict__ out_route)
{
    extern __shared__ char smraw[];
    float* rsm    = (float*)smraw;            // 16032 f : route [r][q][g] (first 16000)
    float* L      = rsm + RSM_F;              // 8160 f : [q][h][g]
    float* Qsm    = L + 8160;                 // 640 f
    u64*   W1t    = (u64*)(Qsm + 640);        // 384 : [i][j] dup
    u64*   W2t    = W1t + 384;                // 128 : [j][h] dup
    u64*   b1d    = W2t + 128;                // 16
    u64*   b2d    = b1d + 16;                 // 8
    u64*   mbarp  = b2d + 8;                  // mbarrier
    // overlays into rsm:
    float* hidbuf = rsm;                      // [16 j][HSTR] (after bulk-store drain)
    float* hp     = rsm;                      // phase 3 (after layer 2)
    u64*   headsd = (u64*)(rsm + 3584);
    u64*   scratch= (u64*)(rsm + 3584 + 1280);

    int t  = threadIdx.x;
    int b  = blockIdx.y;
    int q0 = blockIdx.x * QT;
    uint32_t mbar = smem_u32(mbarp);
    uint32_t rsm_a = smem_u32(rsm);

    // ---- phase 0: stage Q (chunk-permuted), build weight tables, init mbarrier ----
    const float4* Qs = (const float4*)(g_Q + (size_t)(b * Gn + q0) * 128);
    for (int i4 = t; i4 < 160; i4 += 512) {
        float4 v = Qs[i4];
        int q = i4 >> 5, rem = i4 & 31, h = rem >> 2, c = rem & 3;
        int chunk = h * 4 + ((c + (h >> 1)) & 3);
        *(float4*)(Qsm + q * 128 + chunk * 4) = v;
    }
    if (t < 384) {                      // W1t[i*16+j] = dup(W1[j][i])
        int i = t >> 4, j = t & 15;
        float w = W1[j * 24 + i];
        W1t[t] = pk(w, w);
    } else if (t < 512) {               // W2t[j*8+h] = dup(W2[h][j])
        int idx = t - 384, j = idx >> 3, h = idx & 7;
        float w = W2[h * 16 + j];
        W2t[idx] = pk(w, w);
    }
    if (t < 16)  { b1d[t] = pk(b1[t], b1[t]); }
    if (t >= 16 && t < 24) { int i = t - 16; b2d[i] = pk(b2[i], b2[i]); }
    if (t == 0)
        asm volatile("mbarrier.init.shared.b64 [%0], 1;" :: "r"(mbar) : "memory");
    __syncthreads();

    // ---- kick off 16 bulk route loads (one thread) ----
    if (t == 0) {
        asm volatile("mbarrier.arrive.expect_tx.shared.b64 _, [%0], %1;"
                     :: "r"(mbar), "r"(16u * SLAB_BYTES) : "memory");
        const float* base = route + (size_t)(b * Gn + q0) * Gn;
        #pragma unroll
        for (int r = 0; r < 16; r++) {
            asm volatile(
                "cp.async.bulk.shared::cta.global.mbarrier::complete_tx::bytes [%0], [%1], %2, [%3];"
                :: "r"(rsm_a + r * SLAB_BYTES), "l"(base + (size_t)r * 2560000),
                   "r"(SLAB_BYTES), "r"(mbar) : "memory");
        }
    }

    // ---- phase 1a: raw qk -> L (overlaps bulk loads) ----
    for (int u = t; u < 1600; u += 512) {
        int g = u >> 3, h = u & 7;
        const ulonglong2* Kp = (const ulonglong2*)(g_K + (size_t)(b * Gn + g) * 128 + h * 16);
        ulonglong2 kv[4];
        #pragma unroll
        for (int i = 0; i < 4; i++) kv[i] = Kp[i];
        int h2 = h >> 1;
        float* Ld = L + h * LH + g;
        #pragma unroll
        for (int q = 0; q < QT; q++) {
            const float* Qr = Qsm + q * 128;
            u64 a = 0ull;
            #pragma unroll
            for (int c = 0; c < 4; c++) {
                int p = h * 4 + ((c + h2) & 3);
                ulonglong2 qc = *(const ulonglong2*)(Qr + p * 4);
                a = fma2(kv[c].x, qc.x, a);
                a = fma2(kv[c].y, qc.y, a);
            }
            Ld[q * LQ] = hadd(a);
        }
    }
    __syncthreads();
    mbar_wait0(mbar);

    // ---- passthrough: 16 bulk stores smem -> out_route ----
    if (t == 0 && out_route) {
        asm volatile("fence.proxy.async.shared::cta;" ::: "memory");
        float* obase = out_route + (size_t)(b * Gn + q0) * Gn;
        #pragma unroll
        for (int r = 0; r < 16; r++) {
            asm volatile(
                "cp.async.bulk.global.shared::cta.bulk_group [%0], [%1], %2;"
                :: "l"(obase + (size_t)r * 2560000), "r"(rsm_a + r * SLAB_BYTES),
                   "r"(SLAB_BYTES) : "memory");
        }
        asm volatile("cp.async.bulk.commit_group;" ::: "memory");
    }

    // ---- phase 1b layer 1: GEMM hid[16 j][1000 pos], thread tile 8 pos x 4 j ----
    // 125 pos-tiles x 4 j-groups = 500 threads, one round.
    u64 l1acc[4][4];
    int pt = t >> 2, jg = t & 3;
    int q1 = pt / 25, g1 = (pt - q1 * 25) * 8;
    if (t < 500) {
        #pragma unroll
        for (int j = 0; j < 4; j++) {
            u64 bj = b1d[jg * 4 + j];
            #pragma unroll
            for (int p = 0; p < 4; p++) l1acc[j][p] = bj;
        }
        const ulonglong2* W1t2 = (const ulonglong2*)W1t;
        // k = 0..7 : qk rows from L
        #pragma unroll
        for (int k = 0; k < 8; k++) {
            const ulonglong2* xp = (const ulonglong2*)(L + q1 * LQ + k * LH + g1);
            ulonglong2 xa = xp[0], xb = xp[1];
            ulonglong2 w01 = W1t2[k * 8 + jg * 2];
            ulonglong2 w23 = W1t2[k * 8 + jg * 2 + 1];
            #pragma unroll
            for (int j = 0; j < 4; j++) {
                u64 w = (j == 0) ? w01.x : (j == 1) ? w01.y : (j == 2) ? w23.x : w23.y;
                l1acc[j][0] = fma2(xa.x, w, l1acc[j][0]);
                l1acc[j][1] = fma2(xa.y, w, l1acc[j][1]);
                l1acc[j][2] = fma2(xb.x, w, l1acc[j][2]);
                l1acc[j][3] = fma2(xb.y, w, l1acc[j][3]);
            }
        }
        // k = 8..23 : route rows from rsm
        #pragma unroll
        for (int r = 0; r < 16; r++) {
            const ulonglong2* xp = (const ulonglong2*)(rsm + r * 1000 + q1 * 200 + g1);
            ulonglong2 xa = xp[0], xb = xp[1];
            ulonglong2 w01 = W1t2[(8 + r) * 8 + jg * 2];
            ulonglong2 w23 = W1t2[(8 + r) * 8 + jg * 2 + 1];
            #pragma unroll
            for (int j = 0; j < 4; j++) {
                u64 w = (j == 0) ? w01.x : (j == 1) ? w01.y : (j == 2) ? w23.x : w23.y;
                l1acc[j][0] = fma2(xa.x, w, l1acc[j][0]);
                l1acc[j][1] = fma2(xa.y, w, l1acc[j][1]);
                l1acc[j][2] = fma2(xb.x, w, l1acc[j][2]);
                l1acc[j][3] = fma2(xb.y, w, l1acc[j][3]);
            }
        }
        #pragma unroll
        for (int j = 0; j < 4; j++)
            #pragma unroll
            for (int p = 0; p < 4; p++) l1acc[j][p] = relu2(l1acc[j][p]);
    }
    // drain bulk stores, finish all rsm reads, then overlay hidbuf on rsm
    if (t == 0 && out_route)
        asm volatile("cp.async.bulk.wait_group 0;" ::: "memory");
    __syncthreads();
    if (t < 500) {
        #pragma unroll
        for (int j = 0; j < 4; j++) {
            u64* hb = (u64*)(hidbuf + (jg * 4 + j) * HSTR + q1 * 200 + g1);
            hb[0] = l1acc[j][0]; hb[1] = l1acc[j][1];
            hb[2] = l1acc[j][2]; hb[3] = l1acc[j][3];
        }
    }
    __syncthreads();

    // ---- phase 1b layer 2: attn[8 h][1000 pos] -> L, thread tile 8 pos x 2 h ----
    if (t < 500) {
        int hg = t & 3, h0 = hg * 2;
        u64 a0[4], a1[4];
        #pragma unroll
        for (int p = 0; p < 4; p++) { a0[p] = b2d[h0]; a1[p] = b2d[h0 + 1]; }
        #pragma unroll
        for (int j = 0; j < 16; j++) {
            const u64* hx = (const u64*)(hidbuf + j * HSTR + q1 * 200 + g1);
            u64 x0 = hx[0], x1 = hx[1], x2 = hx[2], x3 = hx[3];
            ulonglong2 w = *(const ulonglong2*)(W2t + j * 8 + h0);
            a0[0] = fma2(x0, w.x, a0[0]); a0[1] = fma2(x1, w.x, a0[1]);
            a0[2] = fma2(x2, w.x, a0[2]); a0[3] = fma2(x3, w.x, a0[3]);
            a1[0] = fma2(x0, w.y, a1[0]); a1[1] = fma2(x1, w.y, a1[1]);
            a1[2] = fma2(x2, w.y, a1[2]); a1[3] = fma2(x3, w.y, a1[3]);
        }
        ulonglong2* d0 = (ulonglong2*)(L + q1 * LQ + h0 * LH + g1);
        ulonglong2* d1 = (ulonglong2*)(L + q1 * LQ + (h0 + 1) * LH + g1);
        ulonglong2 s;
        s.x = a0[0]; s.y = a0[1]; d0[0] = s;
        s.x = a0[2]; s.y = a0[3]; d0[1] = s;
        s.x = a1[0]; s.y = a1[1]; d1[0] = s;
        s.x = a1[2]; s.y = a1[3]; d1[1] = s;
    }
    __syncthreads();

    // ---- phase 2: softmax over g, one warp per (q,h) row; 40 rows / 16 warps ----
    {
        int warp = t >> 5, lane = t & 31;
        for (int row = warp; row < 40; row += 16) {
            float* Lr = L + (row >> 3) * LQ + (row & 7) * LH;
            float m = -1e30f;
            for (int i = lane; i < 200; i += 32) m = fmaxf(m, Lr[i]);
            #pragma unroll
            for (int o = 16; o > 0; o >>= 1) m = fmaxf(m, __shfl_xor_sync(0xffffffffu, m, o));
            float s = 0.f;
            for (int i = lane; i < 200; i += 32) { float e = __expf(Lr[i] - m); Lr[i] = e; s += e; }
            #pragma unroll
            for (int o = 16; o > 0; o >>= 1) s += __shfl_xor_sync(0xffffffffu, s, o);
            float inv = 1.f / s;
            for (int i = lane; i < 200; i += 32) Lr[i] *= inv;
        }
    }
    __syncthreads();

    // ---- phase 3: heads[q][hv] = sum_g p[q][h][g] * V[g][hv]; slices {52,52,48,48} ----
    {
        int s = t >> 7, hv = t & 127, h = hv >> 4;
        int base = s * 48 + ((s < 2) ? s * 4 : 8);   // 0, 52, 104, 152
        int len  = (s < 2) ? 52 : 48;
        const float* Vp = g_V + (size_t)(b * Gn + base) * 128 + hv;
        const float* Lh = L + h * LH + base;
        u64 acc[QT];
        #pragma unroll
        for (int q = 0; q < QT; q++) acc[q] = 0ull;
        for (int i = 0; i < len; i += 4) {
            float v0 = Vp[(i + 0) * 128], v1 = Vp[(i + 1) * 128];
            float v2 = Vp[(i + 2) * 128], v3 = Vp[(i + 3) * 128];
            u64 va = pk(v0, v1), vb = pk(v2, v3);
            #pragma unroll
            for (int q = 0; q < QT; q++) {
                ulonglong2 p = *(const ulonglong2*)(Lh + q * LQ + i);
                acc[q] = fma2(p.x, va, acc[q]);
                acc[q] = fma2(p.y, vb, acc[q]);
            }
        }
        float* hpd = hp + (s * 128 + hv) * 7;
        #pragma unroll
        for (int q = 0; q < QT; q++) hpd[q] = hadd(acc[q]);
    }
    __syncthreads();
    if (t < 128) {
        #pragma unroll
        for (int q = 0; q < QT; q++) {
            float v = hp[t * 7 + q] + hp[(128 + t) * 7 + q]
                    + hp[(256 + t) * 7 + q] + hp[(384 + t) * 7 + q];
            headsd[q * 128 + t] = pk(v, v);
        }
    }
    __syncthreads();

    // ---- epilogue: Wo-reuse. 128 threads: (hv-half, e-pair), all q per Wo load ----
    if (t < 128) {
        int half = t >> 6, ep = t & 63;
        const u64* Wop = (const u64*)Wo + ep;        // row stride 64 u64
        u64 acc[QT];
        #pragma unroll
        for (int q = 0; q < QT; q++) acc[q] = 0ull;
        int hv0 = half * 64;
        for (int hv = hv0; hv < hv0 + 64; hv += 2) {
            u64 w0 = Wop[hv * 64];
            u64 w1 = Wop[(hv + 1) * 64];
            #pragma unroll
            for (int q = 0; q < QT; q++) {
                ulonglong2 hh = *(const ulonglong2*)(headsd + q * 128 + hv);
                acc[q] = fma2(hh.x, w0, acc[q]);
                acc[q] = fma2(hh.y, w1, acc[q]);
            }
        }
        #pragma unroll
        for (int q = 0; q < QT; q++) scratch[t * QT + q] = acc[q];
    }
    __syncthreads();
    if (t < 64) {
        #pragma unroll
        for (int q = 0; q < QT; q++) {
            float2 a = up(scratch[t * QT + q]);
            float2 c = up(scratch[(64 + t) * QT + q]);
            float2 r; r.x = a.x + c.x; r.y = a.y + c.y;
            *(float2*)(out + (size_t)(b * Gn + q0 + q) * 128 + t * 2) = r;
        }
    }
}

extern "C" void kernel_launch(void* const* d_in, const int* in_sizes, int n_in,
                              void* d_out, int out_size) {
    const float* h_em  = (const float*)d_in[0];
    const float* route = (const float*)d_in[1];
    const float* Wq    = (const float*)d_in[2];
    const float* Wk    = (const float*)d_in[3];
    const float* Wv    = (const float*)d_in[4];
    const float* W1    = (const float*)d_in[5];
    const float* b1    = (const float*)d_in[6];
    const float* W2    = (const float*)d_in[7];
    const float* b2    = (const float*)d_in[8];
    const float* Wo    = (const float*)d_in[9];
    float* out = (float*)d_out;

    float* out_route = nullptr;
    if (out_size >= 1638400 + 40960000) out_route = out + 1638400;

    static bool attr_done = false;
    if (!attr_done) {
        cudaFuncSetAttribute(proj_kernel, cudaFuncAttributeMaxDynamicSharedMemorySize, SMEM1);
        cudaFuncSetAttribute(main_kernel, cudaFuncAttributeMaxDynamicSharedMemorySize, SMEM2);
        attr_done = true;
    }

    dim3 grid1(4, Bn);
    proj_kernel<<<grid1, 256, SMEM1>>>(h_em, Wq, Wk, Wv);
    dim3 grid2(Gn / QT, Bn);
    main_kernel<<<grid2, 512, SMEM2>>>(route, W1, b1, W2, b2, Wo, out, out_route);
}

// round 14
// speedup vs baseline: 1.0134x; 1.0052x over previous
#include <cuda_runtime.h>
#include <cstdint>

typedef unsigned long long u64;

#define Bn 64
#define Gn 200
#define QT 5
#define LH 204                 // h-stride of L (204 mod 32 = 12 -> conflict-free)
#define LQ (8 * LH)            // 1632 q-stride
#define HSTR 1002              // hidbuf j-stride (1002 mod 32 = 10 -> jg banks distinct)

// ---------------- scratch (static device arrays; no allocation) ----------------
__device__ float g_Q[Bn * Gn * 128];          // [b][g][h*16+k]
__device__ float g_K[Bn * Gn * 128];          // [b][g][h*16+k]
__device__ float g_V[Bn * Gn * 128];          // [b][g][h*16+v]

// ---------------- packed f32x2 helpers ----------------
__device__ __forceinline__ u64 fma2(u64 a, u64 b, u64 c) {
    u64 d; asm("fma.rn.f32x2 %0, %1, %2, %3;" : "=l"(d) : "l"(a), "l"(b), "l"(c)); return d;
}
__device__ __forceinline__ u64 pk(float lo, float hi) {
    u64 d; asm("mov.b64 %0, {%1, %2};" : "=l"(d) : "f"(lo), "f"(hi)); return d;
}
__device__ __forceinline__ float2 up(u64 a) {
    float2 r; asm("mov.b64 {%0, %1}, %2;" : "=f"(r.x), "=f"(r.y) : "l"(a)); return r;
}
__device__ __forceinline__ float hadd(u64 a) { float2 r = up(a); return r.x + r.y; }
__device__ __forceinline__ u64 relu2(u64 a) {
    float2 v = up(a); return pk(fmaxf(v.x, 0.f), fmaxf(v.y, 0.f));
}

__device__ __forceinline__ uint32_t smem_u32(const void* p) {
    uint32_t a;
    asm("{ .reg .u64 t; cvta.to.shared.u64 t, %1; cvt.u32.u64 %0, t; }" : "=r"(a) : "l"(p));
    return a;
}
__device__ __forceinline__ void mbar_wait0(uint32_t mbar) {
    asm volatile(
        "{\n\t.reg .pred P;\n"
        "W%=: mbarrier.try_wait.parity.shared.b64 P, [%0], 0;\n"
        "@!P bra W%=;\n\t}"
        :: "r"(mbar) : "memory");
}

// ================= kernel 1: QKV projections — merged w-loop, single wave =================
#define SMEM1 ((8192 + 8320) * 4)

__global__ __launch_bounds__(256, 3) void proj_kernel(
    const float* __restrict__ h_em, const float* __restrict__ Wq,
    const float* __restrict__ Wk, const float* __restrict__ Wv)
{
    extern __shared__ float sm1[];
    float* Wsm = sm1;            // [d][o_local 64]
    float* xs  = sm1 + 8192;     // [d][gl] stride 65

    int t  = threadIdx.x;
    int tx = t & 15, ty = t >> 4;
    int g0 = blockIdx.x * 50;
    int b  = blockIdx.y;

    const float4* xsrc = (const float4*)(h_em + (size_t)(b * Gn + g0) * 128);
    for (int i4 = t; i4 < 1600; i4 += 256) {
        float4 v = xsrc[i4];
        int gl = i4 >> 5, d4 = (i4 & 31) * 4;
        xs[(d4 + 0) * 65 + gl] = v.x;
        xs[(d4 + 1) * 65 + gl] = v.y;
        xs[(d4 + 2) * 65 + gl] = v.z;
        xs[(d4 + 3) * 65 + gl] = v.w;
    }

    #pragma unroll 1
    for (int w = 0; w < 3; w++) {
        const float* W = (w == 0) ? Wq : (w == 1) ? Wk : Wv;
        float* outp    = (w == 0) ? g_Q : (w == 1) ? g_K : g_V;
        #pragma unroll 1
        for (int wh = 0; wh < 2; wh++) {
            __syncthreads();
            for (int idx = t; idx < 8192; idx += 256) {
                int hl = idx >> 11, d = (idx >> 4) & 127, k = idx & 15;
                Wsm[d * 64 + hl * 16 + k] = W[(wh * 4 + hl) * 2048 + d * 16 + k];
            }
            __syncthreads();

            u64 acc[4][2];
            #pragma unroll
            for (int i = 0; i < 4; i++) { acc[i][0] = 0ull; acc[i][1] = 0ull; }

            const u64* Wp = (const u64*)Wsm;
            #pragma unroll 4
            for (int d = 0; d < 128; d++) {
                u64 wv0 = Wp[d * 32 + tx];
                u64 wv1 = Wp[d * 32 + tx + 16];
                #pragma unroll
                for (int i = 0; i < 4; i++) {
                    float x = xs[d * 65 + i * 16 + ty];
                    u64 xv = pk(x, x);
                    acc[i][0] = fma2(xv, wv0, acc[i][0]);
                    acc[i][1] = fma2(xv, wv1, acc[i][1]);
                }
            }
            #pragma unroll
            for (int i = 0; i < 4; i++) {
                int gl = i * 16 + ty;
                if (gl < 50) {
                    float* op = outp + (size_t)(b * Gn + g0 + gl) * 128 + wh * 64 + tx * 2;
                    *(u64*)op        = acc[i][0];
                    *(u64*)(op + 32) = acc[i][1];
                }
            }
        }
    }
}

// ================= kernel 2: fused; TMA route staging + GEMM-form MLP =================
// grid (40, 64); 512 threads; smem ~103.7 KB/CTA -> 2 CTAs/SM, 32 warps.
#define SLAB_BYTES 4000u        // 5 q x 200 g x 4 B per route channel
#define RSM_F 16032             // 16 slabs of 1000 floats (+pad for hidbuf overlay)
#define SMEM2 ((RSM_F + 8160 + 640) * 4 + (384 + 128 + 16 + 8 + 8) * 8)

__global__ __launch_bounds__(512, 2) void main_kernel(
    const float* __restrict__ route, const float* __restrict__ W1,
    const float* __restrict__ b1, const float* __restrict__ W2,
    const float* __restrict__ b2, const float* __restrict__ Wo,
    float* __restrict__ out, float* __restrict__ out_route)
{
    extern __shared__ char smraw[];
    float* rsm    = (float*)smraw;            // 16032 f : route [r][q][g] (first 16000)
    float* L      = rsm + RSM_F;              // 8160 f : [q][h][g]
    float* Qsm    = L + 8160;                 // 640 f
    u64*   W1t    = (u64*)(Qsm + 640);        // 384 : [i][j] dup
    u64*   W2t    = W1t + 384;                // 128 : [j][h] dup
    u64*   b1d    = W2t + 128;                // 16
    u64*   b2d    = b1d + 16;                 // 8
    u64*   mbarp  = b2d + 8;                  // mbarrier
    // overlays into rsm:
    float* hidbuf = rsm;                      // [16 j][HSTR] (after bulk-store drain)
    float* hp     = rsm;                      // phase 3 (after layer 2)
    u64*   headsd = (u64*)(rsm + 3584);
    u64*   scratch= (u64*)(rsm + 3584 + 1280);

    int t  = threadIdx.x;
    int b  = blockIdx.y;
    int q0 = blockIdx.x * QT;
    uint32_t mbar = smem_u32(mbarp);
    uint32_t rsm_a = smem_u32(rsm);

    // ---- phase 0: stage Q (chunk-permuted), build weight tables, init mbarrier ----
    const float4* Qs = (const float4*)(g_Q + (size_t)(b * Gn + q0) * 128);
    for (int i4 = t; i4 < 160; i4 += 512) {
        float4 v = Qs[i4];
        int q = i4 >> 5, rem = i4 & 31, h = rem >> 2, c = rem & 3;
        int chunk = h * 4 + ((c + (h >> 1)) & 3);
        *(float4*)(Qsm + q * 128 + chunk * 4) = v;
    }
    if (t < 384) {                      // W1t[i*16+j] = dup(W1[j][i])
        int i = t >> 4, j = t & 15;
        float w = W1[j * 24 + i];
        W1t[t] = pk(w, w);
    } else if (t < 512) {               // W2t[j*8+h] = dup(W2[h][j])
        int idx = t - 384, j = idx >> 3, h = idx & 7;
        float w = W2[h * 16 + j];
        W2t[idx] = pk(w, w);
    }
    if (t < 16)  { b1d[t] = pk(b1[t], b1[t]); }
    if (t >= 16 && t < 24) { int i = t - 16; b2d[i] = pk(b2[i], b2[i]); }
    if (t == 0)
        asm volatile("mbarrier.init.shared.b64 [%0], 1;" :: "r"(mbar) : "memory");
    __syncthreads();

    // ---- kick off 16 bulk route loads (one thread) ----
    if (t == 0) {
        asm volatile("mbarrier.arrive.expect_tx.shared.b64 _, [%0], %1;"
                     :: "r"(mbar), "r"(16u * SLAB_BYTES) : "memory");
        const float* base = route + (size_t)(b * Gn + q0) * Gn;
        #pragma unroll
        for (int r = 0; r < 16; r++) {
            asm volatile(
                "cp.async.bulk.shared::cta.global.mbarrier::complete_tx::bytes [%0], [%1], %2, [%3];"
                :: "r"(rsm_a + r * SLAB_BYTES), "l"(base + (size_t)r * 2560000),
                   "r"(SLAB_BYTES), "r"(mbar) : "memory");
        }
    }

    // ---- phase 1a: raw qk -> L (overlaps bulk loads) ----
    for (int u = t; u < 1600; u += 512) {
        int g = u >> 3, h = u & 7;
        const ulonglong2* Kp = (const ulonglong2*)(g_K + (size_t)(b * Gn + g) * 128 + h * 16);
        ulonglong2 kv[4];
        #pragma unroll
        for (int i = 0; i < 4; i++) kv[i] = Kp[i];
        int h2 = h >> 1;
        float* Ld = L + h * LH + g;
        #pragma unroll
        for (int q = 0; q < QT; q++) {
            const float* Qr = Qsm + q * 128;
            u64 a = 0ull;
            #pragma unroll
            for (int c = 0; c < 4; c++) {
                int p = h * 4 + ((c + h2) & 3);
                ulonglong2 qc = *(const ulonglong2*)(Qr + p * 4);
                a = fma2(kv[c].x, qc.x, a);
                a = fma2(kv[c].y, qc.y, a);
            }
            Ld[q * LQ] = hadd(a);
        }
    }
    __syncthreads();
    mbar_wait0(mbar);

    // ---- passthrough: 16 bulk stores smem -> out_route ----
    if (t == 0 && out_route) {
        asm volatile("fence.proxy.async.shared::cta;" ::: "memory");
        float* obase = out_route + (size_t)(b * Gn + q0) * Gn;
        #pragma unroll
        for (int r = 0; r < 16; r++) {
            asm volatile(
                "cp.async.bulk.global.shared::cta.bulk_group [%0], [%1], %2;"
                :: "l"(obase + (size_t)r * 2560000), "r"(rsm_a + r * SLAB_BYTES),
                   "r"(SLAB_BYTES) : "memory");
        }
        asm volatile("cp.async.bulk.commit_group;" ::: "memory");
    }

    // ---- phase 1b layer 1: GEMM hid[16 j][1000 pos], thread tile 8 pos x 4 j ----
    // 125 pos-tiles x 4 j-groups = 500 threads, one round.
    u64 l1acc[4][4];
    int pt = t >> 2, jg = t & 3;
    int q1 = pt / 25, g1 = (pt - q1 * 25) * 8;
    if (t < 500) {
        #pragma unroll
        for (int j = 0; j < 4; j++) {
            u64 bj = b1d[jg * 4 + j];
            #pragma unroll
            for (int p = 0; p < 4; p++) l1acc[j][p] = bj;
        }
        const ulonglong2* W1t2 = (const ulonglong2*)W1t;
        // k = 0..7 : qk rows from L
        #pragma unroll
        for (int k = 0; k < 8; k++) {
            const ulonglong2* xp = (const ulonglong2*)(L + q1 * LQ + k * LH + g1);
            ulonglong2 xa = xp[0], xb = xp[1];
            ulonglong2 w01 = W1t2[k * 8 + jg * 2];
            ulonglong2 w23 = W1t2[k * 8 + jg * 2 + 1];
            #pragma unroll
            for (int j = 0; j < 4; j++) {
                u64 w = (j == 0) ? w01.x : (j == 1) ? w01.y : (j == 2) ? w23.x : w23.y;
                l1acc[j][0] = fma2(xa.x, w, l1acc[j][0]);
                l1acc[j][1] = fma2(xa.y, w, l1acc[j][1]);
                l1acc[j][2] = fma2(xb.x, w, l1acc[j][2]);
                l1acc[j][3] = fma2(xb.y, w, l1acc[j][3]);
            }
        }
        // k = 8..23 : route rows from rsm
        #pragma unroll
        for (int r = 0; r < 16; r++) {
            const ulonglong2* xp = (const ulonglong2*)(rsm + r * 1000 + q1 * 200 + g1);
            ulonglong2 xa = xp[0], xb = xp[1];
            ulonglong2 w01 = W1t2[(8 + r) * 8 + jg * 2];
            ulonglong2 w23 = W1t2[(8 + r) * 8 + jg * 2 + 1];
            #pragma unroll
            for (int j = 0; j < 4; j++) {
                u64 w = (j == 0) ? w01.x : (j == 1) ? w01.y : (j == 2) ? w23.x : w23.y;
                l1acc[j][0] = fma2(xa.x, w, l1acc[j][0]);
                l1acc[j][1] = fma2(xa.y, w, l1acc[j][1]);
                l1acc[j][2] = fma2(xb.x, w, l1acc[j][2]);
                l1acc[j][3] = fma2(xb.y, w, l1acc[j][3]);
            }
        }
        #pragma unroll
        for (int j = 0; j < 4; j++)
            #pragma unroll
            for (int p = 0; p < 4; p++) l1acc[j][p] = relu2(l1acc[j][p]);
    }
    // drain bulk stores, finish all rsm reads, then overlay hidbuf on rsm
    if (t == 0 && out_route)
        asm volatile("cp.async.bulk.wait_group 0;" ::: "memory");
    __syncthreads();
    if (t < 500) {
        #pragma unroll
        for (int j = 0; j < 4; j++) {
            u64* hb = (u64*)(hidbuf + (jg * 4 + j) * HSTR + q1 * 200 + g1);
            hb[0] = l1acc[j][0]; hb[1] = l1acc[j][1];
            hb[2] = l1acc[j][2]; hb[3] = l1acc[j][3];
        }
    }
    __syncthreads();

    // ---- phase 1b layer 2: attn[8 h][1000 pos] -> L, thread tile 8 pos x 2 h ----
    if (t < 500) {
        int hg = t & 3, h0 = hg * 2;
        u64 a0[4], a1[4];
        #pragma unroll
        for (int p = 0; p < 4; p++) { a0[p] = b2d[h0]; a1[p] = b2d[h0 + 1]; }
        #pragma unroll
        for (int j = 0; j < 16; j++) {
            const u64* hx = (const u64*)(hidbuf + j * HSTR + q1 * 200 + g1);
            u64 x0 = hx[0], x1 = hx[1], x2 = hx[2], x3 = hx[3];
            ulonglong2 w = *(const ulonglong2*)(W2t + j * 8 + h0);
            a0[0] = fma2(x0, w.x, a0[0]); a0[1] = fma2(x1, w.x, a0[1]);
            a0[2] = fma2(x2, w.x, a0[2]); a0[3] = fma2(x3, w.x, a0[3]);
            a1[0] = fma2(x0, w.y, a1[0]); a1[1] = fma2(x1, w.y, a1[1]);
            a1[2] = fma2(x2, w.y, a1[2]); a1[3] = fma2(x3, w.y, a1[3]);
        }
        ulonglong2* d0 = (ulonglong2*)(L + q1 * LQ + h0 * LH + g1);
        ulonglong2* d1 = (ulonglong2*)(L + q1 * LQ + (h0 + 1) * LH + g1);
        ulonglong2 s;
        s.x = a0[0]; s.y = a0[1]; d0[0] = s;
        s.x = a0[2]; s.y = a0[3]; d0[1] = s;
        s.x = a1[0]; s.y = a1[1]; d1[0] = s;
        s.x = a1[2]; s.y = a1[3]; d1[1] = s;
    }
    __syncthreads();

    // ---- phase 2: softmax over g, one warp per (q,h) row; 40 rows / 16 warps ----
    {
        int warp = t >> 5, lane = t & 31;
        for (int row = warp; row < 40; row += 16) {
            float* Lr = L + (row >> 3) * LQ + (row & 7) * LH;
            float m = -1e30f;
            for (int i = lane; i < 200; i += 32) m = fmaxf(m, Lr[i]);
            #pragma unroll
            for (int o = 16; o > 0; o >>= 1) m = fmaxf(m, __shfl_xor_sync(0xffffffffu, m, o));
            float s = 0.f;
            for (int i = lane; i < 200; i += 32) { float e = __expf(Lr[i] - m); Lr[i] = e; s += e; }
            #pragma unroll
            for (int o = 16; o > 0; o >>= 1) s += __shfl_xor_sync(0xffffffffu, s, o);
            float inv = 1.f / s;
            for (int i = lane; i < 200; i += 32) Lr[i] *= inv;
        }
    }
    __syncthreads();

    // ---- phase 3: heads[q][hv] = sum_g p[q][h][g] * V[g][hv]; slices {52,52,48,48} ----
    {
        int s = t >> 7, hv = t & 127, h = hv >> 4;
        int base = s * 48 + ((s < 2) ? s * 4 : 8);   // 0, 52, 104, 152
        int len  = (s < 2) ? 52 : 48;
        const float* Vp = g_V + (size_t)(b * Gn + base) * 128 + hv;
        const float* Lh = L + h * LH + base;
        u64 acc[QT];
        #pragma unroll
        for (int q = 0; q < QT; q++) acc[q] = 0ull;
        for (int i = 0; i < len; i += 4) {
            float v0 = Vp[(i + 0) * 128], v1 = Vp[(i + 1) * 128];
            float v2 = Vp[(i + 2) * 128], v3 = Vp[(i + 3) * 128];
            u64 va = pk(v0, v1), vb = pk(v2, v3);
            #pragma unroll
            for (int q = 0; q < QT; q++) {
                ulonglong2 p = *(const ulonglong2*)(Lh + q * LQ + i);
                acc[q] = fma2(p.x, va, acc[q]);
                acc[q] = fma2(p.y, vb, acc[q]);
            }
        }
        float* hpd = hp + (s * 128 + hv) * 7;
        #pragma unroll
        for (int q = 0; q < QT; q++) hpd[q] = hadd(acc[q]);
    }
    __syncthreads();
    if (t < 128) {
        #pragma unroll
        for (int q = 0; q < QT; q++) {
            float v = hp[t * 7 + q] + hp[(128 + t) * 7 + q]
                    + hp[(256 + t) * 7 + q] + hp[(384 + t) * 7 + q];
            headsd[q * 128 + t] = pk(v, v);
        }
    }
    __syncthreads();

    // ---- epilogue: Wo-reuse. 128 threads: (hv-half, e-pair), all q per Wo load ----
    if (t < 128) {
        int half = t >> 6, ep = t & 63;
        const u64* Wop = (const u64*)Wo + ep;        // row stride 64 u64
        u64 acc[QT];
        #pragma unroll
        for (int q = 0; q < QT; q++) acc[q] = 0ull;
        int hv0 = half * 64;
        for (int hv = hv0; hv < hv0 + 64; hv += 2) {
            u64 w0 = Wop[hv * 64];
            u64 w1 = Wop[(hv + 1) * 64];
            #pragma unroll
            for (int q = 0; q < QT; q++) {
                ulonglong2 hh = *(const ulonglong2*)(headsd + q * 128 + hv);
                acc[q] = fma2(hh.x, w0, acc[q]);
                acc[q] = fma2(hh.y, w1, acc[q]);
            }
        }
        #pragma unroll
        for (int q = 0; q < QT; q++) scratch[t * QT + q] = acc[q];
    }
    __syncthreads();
    if (t < 64) {
        #pragma unroll
        for (int q = 0; q < QT; q++) {
            float2 a = up(scratch[t * QT + q]);
            float2 c = up(scratch[(64 + t) * QT + q]);
            float2 r; r.x = a.x + c.x; r.y = a.y + c.y;
            *(float2*)(out + (size_t)(b * Gn + q0 + q) * 128 + t * 2) = r;
        }
    }
}

extern "C" void kernel_launch(void* const* d_in, const int* in_sizes, int n_in,
                              void* d_out, int out_size) {
    const float* h_em  = (const float*)d_in[0];
    const float* route = (const float*)d_in[1];
    const float* Wq    = (const float*)d_in[2];
    const float* Wk    = (const float*)d_in[3];
    const float* Wv    = (const float*)d_in[4];
    const float* W1    = (const float*)d_in[5];
    const float* b1    = (const float*)d_in[6];
    const float* W2    = (const float*)d_in[7];
    const float* b2    = (const float*)d_in[8];
    const float* Wo    = (const float*)d_in[9];
    float* out = (float*)d_out;

    float* out_route = nullptr;
    if (out_size >= 1638400 + 40960000) out_route = out + 1638400;

    static bool attr_done = false;
    if (!attr_done) {
        cudaFuncSetAttribute(proj_kernel, cudaFuncAttributeMaxDynamicSharedMemorySize, SMEM1);
        cudaFuncSetAttribute(main_kernel, cudaFuncAttributeMaxDynamicSharedMemorySize, SMEM2);
        attr_done = true;
    }

    dim3 grid1(4, Bn);
    proj_kernel<<<grid1, 256, SMEM1>>>(h_em, Wq, Wk, Wv);
    dim3 grid2(Gn / QT, Bn);
    main_kernel<<<grid2, 512, SMEM2>>>(route, W1, b1, W2, b2, Wo, out, out_route);
}